// round 1
// baseline (speedup 1.0000x reference)
#include <cuda_runtime.h>
#include <cuda_bf16.h>
#include <cstdint>
#include <math.h>

#define NQ   8192
#define NM   16384
#define DIM  1024
#define KNN  5
#define NCAND 16

// ---------------- static device scratch (no allocations allowed) ----------------
__device__ __nv_bfloat16 g_qbf[(size_t)NQ * DIM];     // 16 MB
__device__ __nv_bfloat16 g_mbf[(size_t)NM * DIM];     // 32 MB
__device__ float         g_q2[NQ];
__device__ float         g_m2[NM];
__device__ __nv_bfloat16 g_S[(size_t)NQ * NM];        // 256 MB similarity scratch
__device__ int           g_cand[NQ * NCAND];

// =============================== prep ===============================
// One warp per row: convert f32 -> bf16 and compute sum of squares.
__global__ void __launch_bounds__(256) prep_kernel(const float* __restrict__ src,
                                                   __nv_bfloat16* __restrict__ dst,
                                                   float* __restrict__ sq, int nrows) {
    int warp = (blockIdx.x * blockDim.x + threadIdx.x) >> 5;
    int lane = threadIdx.x & 31;
    if (warp >= nrows) return;
    const float4* s4 = (const float4*)(src + (size_t)warp * DIM);
    __nv_bfloat162* d2 = (__nv_bfloat162*)(dst + (size_t)warp * DIM);
    float acc = 0.f;
#pragma unroll
    for (int c = 0; c < DIM / 128; ++c) {
        float4 v = s4[c * 32 + lane];
        acc += v.x * v.x + v.y * v.y + v.z * v.z + v.w * v.w;
        d2[(c * 32 + lane) * 2 + 0] = __floats2bfloat162_rn(v.x, v.y);
        d2[(c * 32 + lane) * 2 + 1] = __floats2bfloat162_rn(v.z, v.w);
    }
#pragma unroll
    for (int o = 16; o; o >>= 1) acc += __shfl_xor_sync(0xffffffffu, acc, o);
    if (lane == 0) sq[warp] = acc;
}

// =============================== GEMM ===============================
// S = Q_bf16 @ M_bf16^T, fp32 accumulate, stored as bf16.
// 128x128 CTA tile, BK=32, 8 warps (4x2), warp tile 32x64, mma.sync m16n8k16.
#define BKT  32
#define SSTR 40   // padded smem row stride (elements) -> conflict-free ldmatrix

__device__ __forceinline__ uint32_t smem_u32(const void* p) {
    return (uint32_t)__cvta_generic_to_shared(p);
}
__device__ __forceinline__ void cpasync16(uint32_t s, const void* g) {
    asm volatile("cp.async.cg.shared.global [%0], [%1], 16;\n" :: "r"(s), "l"(g));
}
__device__ __forceinline__ void mma16816(float* c, const uint32_t* a, uint32_t b0, uint32_t b1) {
    asm volatile(
        "mma.sync.aligned.m16n8k16.row.col.f32.bf16.bf16.f32 "
        "{%0,%1,%2,%3}, {%4,%5,%6,%7}, {%8,%9}, {%0,%1,%2,%3};\n"
        : "+f"(c[0]), "+f"(c[1]), "+f"(c[2]), "+f"(c[3])
        : "r"(a[0]), "r"(a[1]), "r"(a[2]), "r"(a[3]), "r"(b0), "r"(b1));
}

__global__ void __launch_bounds__(256, 1) gemm_kernel() {
    __shared__ __nv_bfloat16 As[2][128 * SSTR];
    __shared__ __nv_bfloat16 Bs[2][128 * SSTR];

    const int tid  = threadIdx.x;
    const int wid  = tid >> 5;
    const int lane = tid & 31;
    const int wm = wid >> 1;          // 0..3  -> m offset wm*32
    const int wn = wid & 1;           // 0..1  -> n offset wn*64
    const int m0 = blockIdx.y * 128;
    const int n0 = blockIdx.x * 128;

    const __nv_bfloat16* Ag = g_qbf + (size_t)m0 * DIM;
    const __nv_bfloat16* Bg = g_mbf + (size_t)n0 * DIM;

    const int lrow = tid >> 2;          // 0..63
    const int lcol = (tid & 3) * 8;     // 0,8,16,24

    float acc[2][8][4];
#pragma unroll
    for (int i = 0; i < 2; i++)
#pragma unroll
        for (int j = 0; j < 8; j++)
#pragma unroll
            for (int c = 0; c < 4; c++) acc[i][j][c] = 0.f;

    // prologue: prefetch tile 0 into buf 0
    {
#pragma unroll
        for (int h = 0; h < 2; ++h) {
            int r = lrow + h * 64;
            cpasync16(smem_u32(&As[0][r * SSTR + lcol]), Ag + (size_t)r * DIM + lcol);
            cpasync16(smem_u32(&Bs[0][r * SSTR + lcol]), Bg + (size_t)r * DIM + lcol);
        }
        asm volatile("cp.async.commit_group;\n");
    }

    const int NT = DIM / BKT;   // 32
    for (int kt = 0; kt < NT; ++kt) {
        const int buf = kt & 1;
        if (kt + 1 < NT) {
            const int nb = buf ^ 1;
            const int kc = (kt + 1) * BKT;
#pragma unroll
            for (int h = 0; h < 2; ++h) {
                int r = lrow + h * 64;
                cpasync16(smem_u32(&As[nb][r * SSTR + lcol]), Ag + (size_t)r * DIM + kc + lcol);
                cpasync16(smem_u32(&Bs[nb][r * SSTR + lcol]), Bg + (size_t)r * DIM + kc + lcol);
            }
            asm volatile("cp.async.commit_group;\n");
            asm volatile("cp.async.wait_group 1;\n");
        } else {
            asm volatile("cp.async.wait_group 0;\n");
        }
        __syncthreads();

#pragma unroll
        for (int s = 0; s < 2; ++s) {
            uint32_t af[2][4];
#pragma unroll
            for (int i = 0; i < 2; ++i) {
                int row = wm * 32 + i * 16 + (lane & 15);
                int col = s * 16 + ((lane >> 4) << 3);
                uint32_t addr = smem_u32(&As[buf][row * SSTR + col]);
                asm volatile("ldmatrix.sync.aligned.m8n8.x4.shared.b16 {%0,%1,%2,%3}, [%4];\n"
                             : "=r"(af[i][0]), "=r"(af[i][1]), "=r"(af[i][2]), "=r"(af[i][3])
                             : "r"(addr));
            }
#pragma unroll
            for (int jp = 0; jp < 4; ++jp) {
                uint32_t bfr[4];
                int row = wn * 64 + jp * 16 + (lane & 7) + ((lane & 16) ? 8 : 0);
                int col = s * 16 + ((lane & 8) ? 8 : 0);
                uint32_t addr = smem_u32(&Bs[buf][row * SSTR + col]);
                asm volatile("ldmatrix.sync.aligned.m8n8.x4.shared.b16 {%0,%1,%2,%3}, [%4];\n"
                             : "=r"(bfr[0]), "=r"(bfr[1]), "=r"(bfr[2]), "=r"(bfr[3])
                             : "r"(addr));
#pragma unroll
                for (int i = 0; i < 2; ++i) {
                    mma16816(acc[i][jp * 2 + 0], af[i], bfr[0], bfr[1]);
                    mma16816(acc[i][jp * 2 + 1], af[i], bfr[2], bfr[3]);
                }
            }
        }
        __syncthreads();
    }

    // epilogue: store S as bf16
    const int g = lane >> 2, tig = lane & 3;
#pragma unroll
    for (int i = 0; i < 2; ++i) {
        int row = m0 + wm * 32 + i * 16 + g;
#pragma unroll
        for (int j = 0; j < 8; ++j) {
            int col = n0 + wn * 64 + j * 8 + tig * 2;
            *(__nv_bfloat162*)(g_S + (size_t)row * NM + col) =
                __floats2bfloat162_rn(acc[i][j][0], acc[i][j][1]);
            *(__nv_bfloat162*)(g_S + (size_t)(row + 8) * NM + col) =
                __floats2bfloat162_rn(acc[i][j][2], acc[i][j][3]);
        }
    }
}

// =============================== candidate selection ===============================
// One warp per query row. Score = m2[c] - 2*S[r][c] (q2 is a per-row constant).
// Lane-local top-8 insertion lists, then 16 warp-argmin pops -> top-16 candidates.
__global__ void __launch_bounds__(128) select_kernel() {
    int warp = (blockIdx.x * blockDim.x + threadIdx.x) >> 5;
    int lane = threadIdx.x & 31;
    if (warp >= NQ) return;
    const int r = warp;

    float topv[8];
    int   topi[8];
#pragma unroll
    for (int j = 0; j < 8; ++j) { topv[j] = 3.0e38f; topi[j] = 0; }

    const __nv_bfloat16* Srow = g_S + (size_t)r * NM;
    for (int it = 0; it < NM / 256; ++it) {
        int c0 = it * 256 + lane * 8;
        uint4 raw = *(const uint4*)(Srow + c0);
        float4 m2a = *(const float4*)(g_m2 + c0);
        float4 m2b = *(const float4*)(g_m2 + c0 + 4);
        float2 f0 = __bfloat1622float2(*(__nv_bfloat162*)&raw.x);
        float2 f1 = __bfloat1622float2(*(__nv_bfloat162*)&raw.y);
        float2 f2 = __bfloat1622float2(*(__nv_bfloat162*)&raw.z);
        float2 f3 = __bfloat1622float2(*(__nv_bfloat162*)&raw.w);
        float sv[8]  = {f0.x, f0.y, f1.x, f1.y, f2.x, f2.y, f3.x, f3.y};
        float m2v[8] = {m2a.x, m2a.y, m2a.z, m2a.w, m2b.x, m2b.y, m2b.z, m2b.w};
#pragma unroll
        for (int p = 0; p < 8; ++p) {
            float v = m2v[p] - 2.f * sv[p];
            if (v < topv[7]) {
                topv[7] = v; topi[7] = c0 + p;
#pragma unroll
                for (int j = 7; j > 0; --j) {
                    if (topv[j] < topv[j - 1]) {
                        float tv = topv[j]; topv[j] = topv[j - 1]; topv[j - 1] = tv;
                        int   ti = topi[j]; topi[j] = topi[j - 1]; topi[j - 1] = ti;
                    }
                }
            }
        }
    }

    // 16 warp-argmin pops
    for (int t = 0; t < NCAND; ++t) {
        float mv = topv[0]; int mj = 0;
#pragma unroll
        for (int j = 1; j < 8; ++j) if (topv[j] < mv) { mv = topv[j]; mj = j; }
        float bestv = mv; int bestl = lane;
#pragma unroll
        for (int o = 16; o; o >>= 1) {
            float ov = __shfl_xor_sync(0xffffffffu, bestv, o);
            int   ol = __shfl_xor_sync(0xffffffffu, bestl, o);
            if (ov < bestv || (ov == bestv && ol < bestl)) { bestv = ov; bestl = ol; }
        }
        int myidx = topi[0];
#pragma unroll
        for (int j = 1; j < 8; ++j) if (mj == j) myidx = topi[j];
        int widx = __shfl_sync(0xffffffffu, myidx, bestl);
        if (lane == bestl) {
#pragma unroll
            for (int j = 0; j < 8; ++j) if (j == mj) topv[j] = 3.0e38f;
        }
        if (lane == 0) g_cand[r * NCAND + t] = widx;
    }
}

// =============================== exact rescore + final score ===============================
__global__ void __launch_bounds__(128) final_kernel(const float* __restrict__ query,
                                                    const float* __restrict__ mbank,
                                                    const float* __restrict__ nscale,
                                                    float* __restrict__ out) {
    int warp = (blockIdx.x * blockDim.x + threadIdx.x) >> 5;
    int lane = threadIdx.x & 31;
    if (warp >= NQ) return;
    const int r = warp;

    float4 qv[8];
    const float4* q4 = (const float4*)(query + (size_t)r * DIM);
#pragma unroll
    for (int c = 0; c < 8; ++c) qv[c] = q4[c * 32 + lane];
    const float q2 = g_q2[r];

    float myd = 1e30f; int myidx = 0;
    for (int t = 0; t < NCAND; ++t) {
        int c = g_cand[r * NCAND + t];
        const float4* m4 = (const float4*)(mbank + (size_t)c * DIM);
        float dot = 0.f;
#pragma unroll
        for (int j = 0; j < 8; ++j) {
            float4 mv = m4[j * 32 + lane];
            dot += qv[j].x * mv.x + qv[j].y * mv.y + qv[j].z * mv.z + qv[j].w * mv.w;
        }
#pragma unroll
        for (int o = 16; o; o >>= 1) dot += __shfl_xor_sync(0xffffffffu, dot, o);
        float d2 = q2 + g_m2[c] - 2.f * dot;
        float d  = sqrtf(fmaxf(d2, 1e-12f));
        if (lane == t) { myd = d; myidx = c; }
    }

    // exact top-5 smallest among the 16 candidate lanes
    float dsel[KNN], ssel[KNN];
    float v = myd;
    for (int s = 0; s < KNN; ++s) {
        float bestv = v; int bestl = lane;
#pragma unroll
        for (int o = 16; o; o >>= 1) {
            float ov = __shfl_xor_sync(0xffffffffu, bestv, o);
            int   ol = __shfl_xor_sync(0xffffffffu, bestl, o);
            if (ov < bestv || (ov == bestv && ol < bestl)) { bestv = ov; bestl = ol; }
        }
        int wcand = __shfl_sync(0xffffffffu, myidx, bestl);
        dsel[s] = bestv;
        ssel[s] = nscale[wcand];
        if (lane == bestl) v = 1e30f;
    }

    // final formula (redundant on all lanes, lane0 writes)
    float mean = 0.f, ns = 0.f, dmin = dsel[0];
#pragma unroll
    for (int s = 0; s < KNN; ++s) {
        mean += dsel[s]; ns += ssel[s]; dmin = fminf(dmin, dsel[s]);
    }
    mean *= (1.f / KNN); ns *= (1.f / KNN);
    float W = 0.f, WD = 0.f, var = 0.f;
#pragma unroll
    for (int s = 0; s < KNN; ++s) {
        float w = expf(-(dsel[s] - dmin));   // stabilized softmax(-d)
        W  += w;
        WD += w * dsel[s];
        float dd = dsel[s] - mean;
        var += dd * dd;
    }
    var *= (1.f / KNN);
    float wd    = WD / W;
    float cons  = sqrtf(var) / fmaxf(mean, 1e-6f);
    float normd = wd / fmaxf(ns, 1e-6f);
    if (lane == 0) out[r] = normd * (1.f + 0.5f * cons);
}

// =============================== launch ===============================
extern "C" void kernel_launch(void* const* d_in, const int* in_sizes, int n_in,
                              void* d_out, int out_size) {
    const float* query  = (const float*)d_in[0];
    const float* mbank  = (const float*)d_in[1];
    const float* nscale = (const float*)d_in[2];
    float* out = (float*)d_out;
    (void)in_sizes; (void)n_in; (void)out_size;

    __nv_bfloat16 *qbf_p, *mbf_p;
    float *q2_p, *m2_p;
    cudaGetSymbolAddress((void**)&qbf_p, g_qbf);
    cudaGetSymbolAddress((void**)&mbf_p, g_mbf);
    cudaGetSymbolAddress((void**)&q2_p, g_q2);
    cudaGetSymbolAddress((void**)&m2_p, g_m2);

    // 1) prep: bf16 copies + row sum-of-squares
    prep_kernel<<<NQ / 8, 256>>>(query, qbf_p, q2_p, NQ);
    prep_kernel<<<NM / 8, 256>>>(mbank, mbf_p, m2_p, NM);

    // 2) bf16 similarity GEMM
    dim3 ggrid(NM / 128, NQ / 128);
    gemm_kernel<<<ggrid, 256>>>();

    // 3) top-16 candidate selection per query
    select_kernel<<<NQ / 4, 128>>>();

    // 4) exact fp32 rescore + final score
    final_kernel<<<NQ / 4, 128>>>(query, mbank, nscale, out);
}

// round 3
// speedup vs baseline: 2.1964x; 2.1964x over previous
#include <cuda_runtime.h>
#include <cuda_bf16.h>
#include <cuda_fp16.h>
#include <cstdint>
#include <math.h>

#define NQ   8192
#define NM   16384
#define DIM  1024
#define KNN  5
#define NCAND 16

#define QSCALE 24.0f
#define INV_S2 (1.0f / (24.0f * 24.0f))

// ---------------- static device scratch (no allocations allowed) ----------------
__device__ __align__(256) int8_t g_q8[(size_t)NQ * DIM];      // 8 MB
__device__ __align__(256) int8_t g_m8[(size_t)NM * DIM];      // 16 MB
__device__ __align__(256) float  g_q2[NQ];
__device__ __align__(256) float  g_m2[NM];
__device__ __align__(256) __half g_Sh[(size_t)NQ * NM];       // 256 MB scores d^2-q2 (fp16, >=0)
__device__ __align__(256) int    g_cand[NQ * NCAND];

// =============================== helpers ===============================
__device__ __forceinline__ uint32_t smem_u32(const void* p) {
    return (uint32_t)__cvta_generic_to_shared(p);
}
__device__ __forceinline__ void cpasync16(uint32_t s, const void* g) {
    asm volatile("cp.async.cg.shared.global [%0], [%1], 16;\n" :: "r"(s), "l"(g));
}
__device__ __forceinline__ void mma_s8(int* c, const uint32_t* a, uint32_t b0, uint32_t b1) {
    asm volatile(
        "mma.sync.aligned.m16n8k32.row.col.s32.s8.s8.s32 "
        "{%0,%1,%2,%3}, {%4,%5,%6,%7}, {%8,%9}, {%0,%1,%2,%3};\n"
        : "+r"(c[0]), "+r"(c[1]), "+r"(c[2]), "+r"(c[3])
        : "r"(a[0]), "r"(a[1]), "r"(a[2]), "r"(a[3]), "r"(b0), "r"(b1));
}
__device__ __forceinline__ void ldmx4(uint32_t* r, uint32_t addr) {
    asm volatile("ldmatrix.sync.aligned.m8n8.x4.shared.b16 {%0,%1,%2,%3}, [%4];\n"
                 : "=r"(r[0]), "=r"(r[1]), "=r"(r[2]), "=r"(r[3]) : "r"(addr));
}

// =============================== prep: quantize + row sumsq ===============================
__global__ void __launch_bounds__(256) prep_kernel(const float* __restrict__ src,
                                                   int8_t* __restrict__ dst,
                                                   float* __restrict__ sq, int nrows) {
    int warp = (blockIdx.x * blockDim.x + threadIdx.x) >> 5;
    int lane = threadIdx.x & 31;
    if (warp >= nrows) return;
    const float4* s4 = (const float4*)(src + (size_t)warp * DIM);
    uint32_t* d4 = (uint32_t*)(dst + (size_t)warp * DIM);
    float acc = 0.f;
#pragma unroll
    for (int c = 0; c < DIM / 128; ++c) {
        float4 v = s4[c * 32 + lane];
        acc += v.x * v.x + v.y * v.y + v.z * v.z + v.w * v.w;
        int qa = max(-127, min(127, __float2int_rn(v.x * QSCALE)));
        int qb = max(-127, min(127, __float2int_rn(v.y * QSCALE)));
        int qc = max(-127, min(127, __float2int_rn(v.z * QSCALE)));
        int qd = max(-127, min(127, __float2int_rn(v.w * QSCALE)));
        uint32_t p = (uint32_t)(uint8_t)(int8_t)qa |
                     ((uint32_t)(uint8_t)(int8_t)qb << 8) |
                     ((uint32_t)(uint8_t)(int8_t)qc << 16) |
                     ((uint32_t)(uint8_t)(int8_t)qd << 24);
        d4[c * 32 + lane] = p;
    }
#pragma unroll
    for (int o = 16; o; o >>= 1) acc += __shfl_xor_sync(0xffffffffu, acc, o);
    if (lane == 0) sq[warp] = acc;
}

// =============================== int8 GEMM + score epilogue ===============================
// CTA 128x256, warp tile 64x64 (warp grid 2x4), K stage = 64 bytes, 4 stages.
// smem rows padded to 80B -> conflict-free ldmatrix.
#define BM 128
#define BN 256
#define BKB 64
#define STAGES 4
#define AROW 80
#define A_ST (BM * AROW)                  // 10240
#define B_ST (BN * AROW)                  // 20480
#define STAGE_BYTES (A_ST + B_ST)         // 30720
#define SMEM_DYN (STAGES * STAGE_BYTES)   // 122880
#define KTILES (DIM / BKB)                // 16

__global__ void __launch_bounds__(256, 1) gemm_kernel() {
    extern __shared__ char smem[];
    const uint32_t sb = smem_u32(smem);

    const int tid  = threadIdx.x;
    const int wid  = tid >> 5;
    const int lane = tid & 31;
    const int wm = wid & 1;            // m offset wm*64
    const int wn = wid >> 1;           // n offset wn*64
    const size_t m0 = (size_t)blockIdx.y * BM;
    const size_t n0 = (size_t)blockIdx.x * BN;

    const char* Ag = (const char*)g_q8 + m0 * DIM;
    const char* Bg = (const char*)g_m8 + n0 * DIM;

    int acc[4][8][4];
#pragma unroll
    for (int i = 0; i < 4; ++i)
#pragma unroll
        for (int j = 0; j < 8; ++j)
#pragma unroll
            for (int c = 0; c < 4; ++c) acc[i][j][c] = 0;

    auto load_stage = [&](int t, int s) {
        const uint32_t st = sb + s * STAGE_BYTES;
#pragma unroll
        for (int i = 0; i < 2; ++i) {          // A: 512 16B chunks
            int c = tid + i * 256;
            int r = c >> 2, u = c & 3;
            cpasync16(st + r * AROW + u * 16, Ag + (size_t)r * DIM + t * BKB + u * 16);
        }
#pragma unroll
        for (int i = 0; i < 4; ++i) {          // B: 1024 16B chunks
            int c = tid + i * 256;
            int r = c >> 2, u = c & 3;
            cpasync16(st + A_ST + r * AROW + u * 16, Bg + (size_t)r * DIM + t * BKB + u * 16);
        }
        asm volatile("cp.async.commit_group;\n");
    };

    // prologue: stages 0..2
    load_stage(0, 0);
    load_stage(1, 1);
    load_stage(2, 2);

#pragma unroll 1
    for (int kt = 0; kt < KTILES; ++kt) {
        if (kt <= 13)      asm volatile("cp.async.wait_group 2;\n" ::: "memory");
        else if (kt == 14) asm volatile("cp.async.wait_group 1;\n" ::: "memory");
        else               asm volatile("cp.async.wait_group 0;\n" ::: "memory");
        __syncthreads();

        if (kt + 3 < KTILES) load_stage(kt + 3, (kt + 3) & 3);

        const uint32_t st = sb + (kt & 3) * STAGE_BYTES;
#pragma unroll
        for (int ks = 0; ks < 2; ++ks) {       // two k32 steps per 64B stage
            uint32_t a[4][4], b[4][4];
            const uint32_t aAddr = st + (wm * 64 + (lane & 15)) * AROW
                                 + ks * 32 + ((lane >> 4) << 4);
#pragma unroll
            for (int i = 0; i < 4; ++i) ldmx4(a[i], aAddr + i * 16 * AROW);
            const uint32_t bAddr = st + A_ST
                                 + (wn * 64 + (lane & 7) + ((lane & 16) ? 8 : 0)) * AROW
                                 + ks * 32 + ((lane & 8) ? 16 : 0);
#pragma unroll
            for (int j = 0; j < 4; ++j) ldmx4(b[j], bAddr + j * 16 * AROW);
#pragma unroll
            for (int i = 0; i < 4; ++i)
#pragma unroll
                for (int j = 0; j < 4; ++j) {
                    mma_s8(acc[i][2 * j + 0], a[i], b[j][0], b[j][1]);
                    mma_s8(acc[i][2 * j + 1], a[i], b[j][2], b[j][3]);
                }
        }
    }

    // ---- epilogue: v = m2[col] - 2*dot*INV_S2, clamp >= 0, store fp16 ----
    const int g = lane >> 2, tig = lane & 3;
    const float* m2base = g_m2 + n0 + wn * 64;
#pragma unroll
    for (int i = 0; i < 4; ++i) {
        size_t row = m0 + wm * 64 + i * 16 + g;
        __half* o0 = g_Sh + row * NM + n0 + wn * 64;
        __half* o1 = o0 + (size_t)8 * NM;
#pragma unroll
        for (int j = 0; j < 8; ++j) {
            int col = j * 8 + 2 * tig;
            float2 m2v = *(const float2*)(m2base + col);
            float v00 = fmaxf(m2v.x - 2.f * INV_S2 * __int2float_rn(acc[i][j][0]), 0.f);
            float v01 = fmaxf(m2v.y - 2.f * INV_S2 * __int2float_rn(acc[i][j][1]), 0.f);
            float v10 = fmaxf(m2v.x - 2.f * INV_S2 * __int2float_rn(acc[i][j][2]), 0.f);
            float v11 = fmaxf(m2v.y - 2.f * INV_S2 * __int2float_rn(acc[i][j][3]), 0.f);
            *(__half2*)(o0 + col) = __floats2half2_rn(v00, v01);
            *(__half2*)(o1 + col) = __floats2half2_rn(v10, v11);
        }
    }
}

// =============================== candidate selection (uint keys) ===============================
// One warp per query row. fp16 scores >= 0 -> raw bits order == value order.
// key = (bits<<16)|col. Lane-local top-8 insertion, then 16 warp-min pops.
__global__ void __launch_bounds__(256) select_kernel() {
    int warp = (blockIdx.x * blockDim.x + threadIdx.x) >> 5;
    int lane = threadIdx.x & 31;
    if (warp >= NQ) return;
    const __half* Srow = g_Sh + (size_t)warp * NM;

    uint32_t top[8];
#pragma unroll
    for (int j = 0; j < 8; ++j) top[j] = 0xFFFFFFFFu;

    for (int it = 0; it < NM / 256; ++it) {
        int c0 = it * 256 + lane * 8;
        uint4 raw = *(const uint4*)(Srow + c0);
        uint32_t w[4] = { raw.x, raw.y, raw.z, raw.w };
#pragma unroll
        for (int q = 0; q < 4; ++q) {
            uint32_t klo = (w[q] << 16) | (uint32_t)(c0 + 2 * q);
            uint32_t khi = (w[q] & 0xFFFF0000u) | (uint32_t)(c0 + 2 * q + 1);
#pragma unroll
            for (int s = 0; s < 2; ++s) {
                uint32_t key = s ? khi : klo;
                if (key < top[7]) {
                    top[7] = key;
#pragma unroll
                    for (int j = 7; j > 0; --j) {
                        if (top[j] < top[j - 1]) { uint32_t t2 = top[j]; top[j] = top[j - 1]; top[j - 1] = t2; }
                    }
                }
            }
        }
    }

    for (int t = 0; t < NCAND; ++t) {
        uint32_t mv = top[0];
#pragma unroll
        for (int j = 1; j < 8; ++j) mv = min(mv, top[j]);
        uint32_t best = mv;
#pragma unroll
        for (int o = 16; o; o >>= 1) best = min(best, __shfl_xor_sync(0xffffffffu, best, o));
        if (lane == 0) g_cand[warp * NCAND + t] = (int)(best & 0xFFFFu);
        if (mv == best) {
#pragma unroll
            for (int j = 0; j < 8; ++j) if (top[j] == best) top[j] = 0xFFFFFFFFu;
        }
    }
}

// =============================== exact rescore + final score ===============================
__global__ void __launch_bounds__(128) final_kernel(const float* __restrict__ query,
                                                    const float* __restrict__ mbank,
                                                    const float* __restrict__ nscale,
                                                    float* __restrict__ out) {
    int warp = (blockIdx.x * blockDim.x + threadIdx.x) >> 5;
    int lane = threadIdx.x & 31;
    if (warp >= NQ) return;
    const int r = warp;

    float4 qv[8];
    const float4* q4 = (const float4*)(query + (size_t)r * DIM);
#pragma unroll
    for (int c = 0; c < 8; ++c) qv[c] = q4[c * 32 + lane];
    const float q2 = g_q2[r];

    float myd = 1e30f; int myidx = 0;
    for (int t = 0; t < NCAND; ++t) {
        int c = g_cand[r * NCAND + t];
        const float4* m4 = (const float4*)(mbank + (size_t)c * DIM);
        float dot = 0.f;
#pragma unroll
        for (int j = 0; j < 8; ++j) {
            float4 mv = m4[j * 32 + lane];
            dot += qv[j].x * mv.x + qv[j].y * mv.y + qv[j].z * mv.z + qv[j].w * mv.w;
        }
#pragma unroll
        for (int o = 16; o; o >>= 1) dot += __shfl_xor_sync(0xffffffffu, dot, o);
        float d2 = q2 + g_m2[c] - 2.f * dot;
        float d  = sqrtf(fmaxf(d2, 1e-12f));
        if (lane == t) { myd = d; myidx = c; }
    }

    float dsel[KNN], ssel[KNN];
    float v = myd;
    for (int s = 0; s < KNN; ++s) {
        float bestv = v; int bestl = lane;
#pragma unroll
        for (int o = 16; o; o >>= 1) {
            float ov = __shfl_xor_sync(0xffffffffu, bestv, o);
            int   ol = __shfl_xor_sync(0xffffffffu, bestl, o);
            if (ov < bestv || (ov == bestv && ol < bestl)) { bestv = ov; bestl = ol; }
        }
        int wcand = __shfl_sync(0xffffffffu, myidx, bestl);
        dsel[s] = bestv;
        ssel[s] = nscale[wcand];
        if (lane == bestl) v = 1e30f;
    }

    float mean = 0.f, ns = 0.f, dmin = dsel[0];
#pragma unroll
    for (int s = 0; s < KNN; ++s) { mean += dsel[s]; ns += ssel[s]; dmin = fminf(dmin, dsel[s]); }
    mean *= (1.f / KNN); ns *= (1.f / KNN);
    float W = 0.f, WD = 0.f, var = 0.f;
#pragma unroll
    for (int s = 0; s < KNN; ++s) {
        float w = expf(-(dsel[s] - dmin));
        W += w; WD += w * dsel[s];
        float dd = dsel[s] - mean; var += dd * dd;
    }
    var *= (1.f / KNN);
    float wd    = WD / W;
    float cons  = sqrtf(var) / fmaxf(mean, 1e-6f);
    float normd = wd / fmaxf(ns, 1e-6f);
    if (lane == 0) out[r] = normd * (1.f + 0.5f * cons);
}

// =============================== launch ===============================
extern "C" void kernel_launch(void* const* d_in, const int* in_sizes, int n_in,
                              void* d_out, int out_size) {
    const float* query  = (const float*)d_in[0];
    const float* mbank  = (const float*)d_in[1];
    const float* nscale = (const float*)d_in[2];
    float* out = (float*)d_out;
    (void)in_sizes; (void)n_in; (void)out_size;

    int8_t *q8_p, *m8_p;
    float *q2_p, *m2_p;
    cudaGetSymbolAddress((void**)&q8_p, g_q8);
    cudaGetSymbolAddress((void**)&m8_p, g_m8);
    cudaGetSymbolAddress((void**)&q2_p, g_q2);
    cudaGetSymbolAddress((void**)&m2_p, g_m2);

    static int smem_set = 0;
    if (!smem_set) {
        cudaFuncSetAttribute(gemm_kernel, cudaFuncAttributeMaxDynamicSharedMemorySize, SMEM_DYN);
        smem_set = 1;
    }

    // 1) quantize + row sum-of-squares
    prep_kernel<<<NQ / 8, 256>>>(query, q8_p, q2_p, NQ);
    prep_kernel<<<NM / 8, 256>>>(mbank, m8_p, m2_p, NM);

    // 2) int8 similarity GEMM + fp16 score epilogue
    dim3 ggrid(NM / BN, NQ / BM);
    gemm_kernel<<<ggrid, 256, SMEM_DYN>>>();

    // 3) top-16 candidate selection per query
    select_kernel<<<NQ / 8, 256>>>();

    // 4) exact fp32 rescore + final score
    final_kernel<<<NQ / 4, 128>>>(query, mbank, nscale, out);
}